// round 15
// baseline (speedup 1.0000x reference)
#include <cuda_runtime.h>
#include <cuda_bf16.h>
#include <cstdint>

constexpr int TIMESTEPS = 1000;
constexpr int B = 4;
constexpr int N = 2048;                                // power of two
constexpr long long E = (long long)N * (N - 1) / 2;    // 2,096,128
constexpr int EI = (int)E;
constexpr int NPAIR = B * (N / 2);                     // 4096 work pairs
constexpr int GRID = 740;                              // 148 SMs x 5 CTAs
constexpr int NTHR = 256;

// Per-buffer SMEM word layout: adj[2056] | u[2056] = 4112 words (q not staged)
constexpr int W_U  = 2056;
constexpr int BUFW = 4112;
constexpr int BUFB = BUFW * 4;                         // 16448 bytes, 16B-aligned
constexpr int SMEM_DYN = 2 * BUFB;                     // 32896 bytes

// Cross-block reduction scratch. g_count self-resets (atomicInc wrap) -> graph-replay safe.
__device__ float        g_partials[GRID];
__device__ unsigned int g_count = 0;

struct Consts { float flip_t, omt, qt00, qt01, qt10, qt11; };

__device__ __forceinline__ float ex2(float x) {
    float r; asm("ex2.approx.f32 %0, %1;" : "=f"(r) : "f"(x)); return r;
}
__device__ __forceinline__ float rcp(float x) {
    float r; asm("rcp.approx.f32 %0, %1;" : "=f"(r) : "f"(x)); return r;
}
// 16B global->shared async copy, L1-bypass (cg).
__device__ __forceinline__ void cpa16(uint32_t dst, const void* src) {
    asm volatile("cp.async.cg.shared.global [%0], [%1], 16;" :: "r"(dst), "l"(src));
}

// Per-element loss term: qt via 4-entry LUT on (a!=0, x1); MUFU softplus.
__device__ __forceinline__ float term(int a, float uu, float x, const Consts& c) {
    bool  ab = (a != 0);
    float pa = ab ? c.omt : c.flip_t;          // Qt[t][a, 1]
    bool  x1 = uu < pa;                        // sampled bit
    float q0 = ab ? c.qt10 : c.qt00;
    float q1 = ab ? c.qt11 : c.qt01;
    float qt = x1 ? q1 : q0;
    float sp = __logf(1.0f + __expf(-fabsf(x)));   // log1p(exp(-|x|))
    return fmaf(-x, qt, fmaxf(x, 0.0f) + sp);
}

__device__ __forceinline__ float term4(int4 A, float4 U,
                                       float x0, float x1, float x2, float x3,
                                       const Consts& c) {
    return term(A.x, U.x, x0, c) + term(A.y, U.y, x1, c)
         + term(A.z, U.z, x2, c) + term(A.w, U.w, x3, c);
}

// Pair geometry: pair pid = (b, k) covers rows i=k (iA<=1023) and i=N-1-k
// (iB in [1024, 2047]); iA+iB = 2047 elements.
struct Geom {
    int iA, iB, rowbaseA, rowbaseB, qrowA, qrowB, cA, cB, cA4, b;
};
__device__ __forceinline__ Geom mk_geom(int pid) {
    Geom g;
    g.b  = pid >> 10;
    int k = pid & 1023;
    g.iA = k;  g.iB = N - 1 - k;
    g.rowbaseA = ((g.b << 11) + g.iA) << 11;
    g.rowbaseB = ((g.b << 11) + g.iB) << 11;
    g.qrowA = g.b * EI + ((g.iA * (g.iA - 1)) >> 1);
    g.qrowB = g.b * EI + ((g.iB * (g.iB - 1)) >> 1);
    g.cA  = (g.iA + 3) >> 2;  g.cB = (g.iB + 3) >> 2;  g.cA4 = g.cA << 2;
    return g;
}

// Stage adj+u for one pair into the SMEM buffer at shared-address s0.
// Chunks stay inside their 2048-element rows (no buffer-end hazards).
__device__ __forceinline__ void stage_pair(const Geom& g,
                                           const int* __restrict__ adj,
                                           const float* __restrict__ u,
                                           uint32_t s0, int tid, int wb) {
    const uint32_t sa = s0, su = s0 + W_U * 4;
    const uint32_t saB = sa + g.cA4 * 4, suB = su + g.cA4 * 4;
    const char* gaB = (const char*)(adj + g.rowbaseB);
    const char* guB = (const char*)(u   + g.rowbaseB);
    const char* gaA = (const char*)(adj + g.rowbaseA);
    const char* guA = (const char*)(u   + g.rowbaseA);

    // row B streams (cB >= 256 -> first slot unconditional)
    cpa16(saB + tid * 16, gaB + tid * 16);
    cpa16(suB + tid * 16, guB + tid * 16);
    if (256 + wb < g.cB) {                       // warp-uniform
        int cc = min(tid + 256, g.cB - 1);       // dup-clamp: benign
        cpa16(saB + cc * 16, gaB + cc * 16);
        cpa16(suB + cc * 16, guB + cc * 16);
    }
    // row A streams
    if (wb < g.cA) {
        int cc = min(tid, g.cA - 1);
        cpa16(sa + cc * 16, gaA + cc * 16);
        cpa16(su + cc * 16, guA + cc * 16);
    }
}

// Compute one staged pair: adj/u from SMEM (LDS.128), q direct from global
// with streaming loads (__ldcs, zero reuse -> evict-first).
__device__ __forceinline__ float compute_pair(const Geom& g, const char* sbuf,
                                              const int* __restrict__ t,
                                              const float* __restrict__ q, int tid) {
    Consts c;
    {
        const float L2_098 = -0.0291463173f;               // log2(0.98)
        int   tb = t[g.b];
        float pt = ex2((float)(tb + 1) * L2_098);          // 0.98^(t+1)
        int   tm1 = (tb + TIMESTEPS - 1) % TIMESTEPS;      // Qt[t-1] wraps at t=0
        float pp = ex2((float)(tm1 + 1) * L2_098);
        c.flip_t = 0.5f - 0.5f * pt;
        c.omt    = 0.5f + 0.5f * pt;
        float flip_p = 0.5f - 0.5f * pp;
        float omp    = 0.5f + 0.5f * pp;
        float r_omt  = rcp(c.omt);
        float r_flip = rcp(c.flip_t);
        // qt[ab][x1] = Qt0[x1,1] * Qt[t-1][ab,1] / Qt[t][ab,x1]
        c.qt00 = 0.01f * flip_p * r_omt;
        c.qt01 = 0.99f * flip_p * r_flip;
        c.qt10 = 0.01f * omp    * r_flip;
        c.qt11 = 0.99f * omp    * r_omt;
    }

    const int*   s_adj = (const int*)sbuf;
    const float* s_u   = (const float*)(sbuf + W_U * 4);

    float s = 0.0f;
    {   // row B: 4-element vector groups (nfB in [256, 511])
        const int nfB = g.iB >> 2, remB = g.iB & 3;
        const int4*   aB4 = reinterpret_cast<const int4*>(s_adj + g.cA4);
        const float4* uB4 = reinterpret_cast<const float4*>(s_u + g.cA4);
        const float*  qB  = q + g.qrowB;

        // group 0: always full. Issue the 4 global q loads first.
        const int e0 = tid << 2;
        float x0 = __ldcs(qB + e0),     x1 = __ldcs(qB + e0 + 1);
        float x2 = __ldcs(qB + e0 + 2), x3 = __ldcs(qB + e0 + 3);
        int4   A1 = aB4[tid];
        float4 U1 = uB4[tid];
        s += term4(A1, U1, x0, x1, x2, x3, c);

        // group 1: predicated (divergent in at most one warp)
        const int g1 = tid + 256;
        if (g1 < nfB) {
            const int e1 = g1 << 2;
            float y0 = __ldcs(qB + e1),     y1 = __ldcs(qB + e1 + 1);
            float y2 = __ldcs(qB + e1 + 2), y3 = __ldcs(qB + e1 + 3);
            s += term4(aB4[g1], uB4[g1], y0, y1, y2, y3, c);
        }
        // tail: <= 3 threads
        if (tid < remB) {
            int e = (nfB << 2) + tid;
            s += term(s_adj[g.cA4 + e], s_u[g.cA4 + e], __ldcs(qB + e), c);
        }
    }
    {   // row A: 4-element vector groups (nfA <= 255)
        const int nfA = g.iA >> 2, remA = g.iA & 3;
        const int4*   aA4 = reinterpret_cast<const int4*>(s_adj);
        const float4* uA4 = reinterpret_cast<const float4*>(s_u);
        const float*  qA  = q + g.qrowA;

        if (tid < nfA) {
            const int e0 = tid << 2;
            float x0 = __ldcs(qA + e0),     x1 = __ldcs(qA + e0 + 1);
            float x2 = __ldcs(qA + e0 + 2), x3 = __ldcs(qA + e0 + 3);
            s += term4(aA4[tid], uA4[tid], x0, x1, x2, x3, c);
        }
        if (tid < remA) {
            int e = (nfA << 2) + tid;
            s += term(s_adj[e], s_u[e], __ldcs(qA + e), c);
        }
    }
    return s;
}

// Persistent CTAs (grid = 148x5), double-buffered cp.async pipeline across
// pairs: stage pair j+1, wait for pair j, compute pair j.
__global__ __launch_bounds__(NTHR, 5)
void loss_kernel(const int* __restrict__ adj, const int* __restrict__ t,
                 const float* __restrict__ u, const float* __restrict__ q,
                 float* __restrict__ out) {
    extern __shared__ char smem[];
    __shared__ float warp_sums[8];
    __shared__ bool  is_last;

    const int tid  = threadIdx.x;
    const int wb   = tid & ~31;
    const int bidx = blockIdx.x;
    const uint32_t s0 = (uint32_t)__cvta_generic_to_shared(smem);

    const int npairs = (NPAIR - 1 - bidx) / GRID + 1;   // 6 or 5

    int  pid = bidx;
    Geom gcur = mk_geom(pid);
    stage_pair(gcur, adj, u, s0, tid, wb);
    asm volatile("cp.async.commit_group;" ::: "memory");

    float s = 0.0f;
    for (int j = 0; j < npairs; ++j) {
        if (j) __syncthreads();                          // prev compute done before restage
        Geom gnext;
        if (j + 1 < npairs) {
            gnext = mk_geom(pid + GRID);
            stage_pair(gnext, adj, u, s0 + ((j + 1) & 1) * BUFB, tid, wb);
        }
        asm volatile("cp.async.commit_group;" ::: "memory");   // may be empty: keeps counts aligned
        asm volatile("cp.async.wait_group 1;" ::: "memory");   // pair j ready; j+1 in flight
        __syncthreads();
        s += compute_pair(gcur, smem + (j & 1) * BUFB, t, q, tid);
        gcur = gnext;
        pid += GRID;
    }
    asm volatile("cp.async.wait_group 0;" ::: "memory");  // drain before exit

    // Block reduction
    #pragma unroll
    for (int off = 16; off; off >>= 1) s += __shfl_down_sync(0xffffffffu, s, off);
    const int lane = tid & 31, wid = tid >> 5;
    if (lane == 0) warp_sums[wid] = s;
    __syncthreads();
    if (wid == 0) {
        s = (lane < 8) ? warp_sums[lane] : 0.0f;
        #pragma unroll
        for (int off = 4; off; off >>= 1) s += __shfl_down_sync(0xffffffffu, s, off);
        if (lane == 0) g_partials[bidx] = s;
    }

    // Last-block-standing final reduction (counter wraps to 0 -> replayable)
    __threadfence();
    if (tid == 0) {
        unsigned v = atomicInc(&g_count, GRID - 1);
        is_last = (v == GRID - 1);
    }
    __syncthreads();
    if (is_last) {
        float acc = 0.0f;
        for (int idx = tid; idx < GRID; idx += NTHR) acc += g_partials[idx];
        #pragma unroll
        for (int off = 16; off; off >>= 1) acc += __shfl_down_sync(0xffffffffu, acc, off);
        if (lane == 0) warp_sums[wid] = acc;
        __syncthreads();
        if (wid == 0) {
            acc = (lane < 8) ? warp_sums[lane] : 0.0f;
            #pragma unroll
            for (int off = 4; off; off >>= 1) acc += __shfl_down_sync(0xffffffffu, acc, off);
            if (lane == 0) out[0] = acc * (1.0f / (float)(B * E));
        }
    }
}

extern "C" void kernel_launch(void* const* d_in, const int* in_sizes, int n_in,
                              void* d_out, int out_size) {
    // metadata order: adj_start (int32), t (int32), u (f32), q_approx (f32)
    const int*   adj = (const int*)d_in[0];
    const int*   t   = (const int*)d_in[1];
    const float* u   = (const float*)d_in[2];
    const float* q   = (const float*)d_in[3];
    float* out = (float*)d_out;

    // Function attributes (context-level, capture-legal, no allocation).
    cudaFuncSetAttribute(loss_kernel,
                         cudaFuncAttributeMaxDynamicSharedMemorySize, SMEM_DYN);
    cudaFuncSetAttribute(loss_kernel,
                         cudaFuncAttributePreferredSharedMemoryCarveout,
                         cudaSharedmemCarveoutMaxShared);

    loss_kernel<<<GRID, NTHR, SMEM_DYN>>>(adj, t, u, q, out);
}

// round 16
// speedup vs baseline: 1.2081x; 1.2081x over previous
#include <cuda_runtime.h>
#include <cuda_bf16.h>
#include <cstdint>

constexpr int TIMESTEPS = 1000;
constexpr int B = 4;
constexpr int N = 2048;                                // power of two
constexpr long long E = (long long)N * (N - 1) / 2;    // 2,096,128
constexpr int EI = (int)E;
constexpr int NPAIR = B * (N / 2);                     // 4096 work pairs
constexpr int GRID = 592;                              // 148 SMs x 4 CTAs
constexpr int NTHR = 256;

// Per-buffer SMEM word layout: adj[2056] | u[2056] | q[2064] = 6176 words
constexpr int W_U   = 2056;
constexpr int W_Q   = 4112;
constexpr int BUFW  = 6176;
constexpr int BUFB  = BUFW * 4;                        // 24704 B, 16B-aligned
constexpr int SMEM_DYN = 2 * BUFB;                     // 49408 B

// Cross-block reduction scratch. g_count self-resets (atomicInc wrap) -> graph-replay safe.
__device__ float        g_partials[GRID];
__device__ unsigned int g_count = 0;

struct Consts { float flip_t, omt, qt00, qt01, qt10, qt11; };

__device__ __forceinline__ float ex2(float x) {
    float r; asm("ex2.approx.f32 %0, %1;" : "=f"(r) : "f"(x)); return r;
}
__device__ __forceinline__ float rcp(float x) {
    float r; asm("rcp.approx.f32 %0, %1;" : "=f"(r) : "f"(x)); return r;
}

// TMA bulk copy: global -> shared::cta, completion counted on an mbarrier.
__device__ __forceinline__ void bulk(uint32_t dst, const void* src, uint32_t bytes,
                                     uint32_t mbar) {
    asm volatile("cp.async.bulk.shared::cta.global.mbarrier::complete_tx::bytes "
                 "[%0], [%1], %2, [%3];"
                 :: "r"(dst), "l"(src), "r"(bytes), "r"(mbar) : "memory");
}
__device__ __forceinline__ void mbar_init(uint32_t mbar, uint32_t cnt) {
    asm volatile("mbarrier.init.shared.b64 [%0], %1;" :: "r"(mbar), "r"(cnt) : "memory");
}
__device__ __forceinline__ void mbar_expect(uint32_t mbar, uint32_t bytes) {
    asm volatile("mbarrier.arrive.expect_tx.shared.b64 _, [%0], %1;"
                 :: "r"(mbar), "r"(bytes) : "memory");
}
__device__ __forceinline__ void mbar_wait(uint32_t mbar, uint32_t parity) {
    asm volatile(
        "{\n\t.reg .pred P;\n\t"
        "W_%=:\n\t"
        "mbarrier.try_wait.parity.acquire.cta.shared::cta.b64 P, [%0], %1, 0x989680;\n\t"
        "@P bra D_%=;\n\t"
        "bra W_%=;\n\t"
        "D_%=:\n\t}"
        :: "r"(mbar), "r"(parity) : "memory");
}

// Per-element loss term: qt via 4-entry LUT on (a!=0, x1); MUFU softplus.
__device__ __forceinline__ float term(int a, float uu, float x, const Consts& c) {
    bool  ab = (a != 0);
    float pa = ab ? c.omt : c.flip_t;          // Qt[t][a, 1]
    bool  x1 = uu < pa;                        // sampled bit
    float q0 = ab ? c.qt10 : c.qt00;
    float q1 = ab ? c.qt11 : c.qt01;
    float qt = x1 ? q1 : q0;
    float sp = __logf(1.0f + __expf(-fabsf(x)));   // log1p(exp(-|x|))
    return fmaf(-x, qt, fmaxf(x, 0.0f) + sp);
}

__device__ __forceinline__ float term4(int4 A, float4 U, const float* qp, const Consts& c) {
    return term(A.x, U.x, qp[0], c) + term(A.y, U.y, qp[1], c)
         + term(A.z, U.z, qp[2], c) + term(A.w, U.w, qp[3], c);
}

// Pair geometry: pair pid = (b, k) covers rows i=k (iA<=1023) and i=N-1-k
// (iB in [1024, 2047]); iA+iB = 2047 elements.
struct Geom {
    int iA, iB, rowbaseA, rowbaseB, cA, cB, cA4;
    int galA, ofsA, galB, ofsB, cqA, cqB, cqA4;
    int b;
};
__device__ __forceinline__ Geom mk_geom(int pid) {
    Geom g;
    g.b  = pid >> 10;
    int k = pid & 1023;
    g.iA = k;  g.iB = N - 1 - k;
    g.rowbaseA = ((g.b << 11) + g.iA) << 11;
    g.rowbaseB = ((g.b << 11) + g.iB) << 11;
    int qrowA = g.b * EI + ((g.iA * (g.iA - 1)) >> 1);
    int qrowB = g.b * EI + ((g.iB * (g.iB - 1)) >> 1);
    g.cA  = (g.iA + 3) >> 2;  g.cB = (g.iB + 3) >> 2;  g.cA4 = g.cA << 2;
    g.galA = qrowA & ~3;  g.ofsA = qrowA & 3;
    g.galB = qrowB & ~3;  g.ofsB = qrowB & 3;
    // cqA forced 0 when iA==0 (b*EI is 4-aligned so ofsA==0 there anyway)
    g.cqA = g.iA ? ((g.iA + g.ofsA + 3) >> 2) : 0;
    g.cqB = (g.iB + g.ofsB + 3) >> 2;
    g.cqA4 = g.cqA << 2;
    return g;
}

// Single-thread TMA staging of one pair into the buffer at shared-addr s0.
// adj/u segments stay inside their 8KB rows; the q segment's 16B rounding can
// over-read <=12B past the q buffer only on the last rows (stays within the
// mapped allocation; those smem slots are never consumed).
__device__ __forceinline__ void produce(const Geom& g,
                                        const int* __restrict__ adj,
                                        const float* __restrict__ u,
                                        const float* __restrict__ q,
                                        uint32_t s0, uint32_t mbar) {
    const uint32_t bytes = (uint32_t)(2 * (g.cA + g.cB) + g.cqA + g.cqB) * 16u;
    mbar_expect(mbar, bytes);
    const uint32_t sa = s0, su = s0 + W_U * 4, sq = s0 + W_Q * 4;
    if (g.cA) {
        bulk(sa, adj + g.rowbaseA, g.cA * 16u, mbar);
        bulk(su, u   + g.rowbaseA, g.cA * 16u, mbar);
        bulk(sq, q   + g.galA,     g.cqA * 16u, mbar);
    }
    bulk(sa + g.cA4 * 4,  adj + g.rowbaseB, g.cB * 16u, mbar);
    bulk(su + g.cA4 * 4,  u   + g.rowbaseB, g.cB * 16u, mbar);
    bulk(sq + g.cqA4 * 4, q   + g.galB,     g.cqB * 16u, mbar);
}

// Compute one staged pair from SMEM (proven R14 body).
__device__ __forceinline__ float compute_pair(const Geom& g, const char* sbuf,
                                              const int* __restrict__ t, int tid) {
    Consts c;
    {
        const float L2_098 = -0.0291463173f;               // log2(0.98)
        int   tb = t[g.b];
        float pt = ex2((float)(tb + 1) * L2_098);          // 0.98^(t+1)
        int   tm1 = (tb + TIMESTEPS - 1) % TIMESTEPS;      // Qt[t-1] wraps at t=0
        float pp = ex2((float)(tm1 + 1) * L2_098);
        c.flip_t = 0.5f - 0.5f * pt;
        c.omt    = 0.5f + 0.5f * pt;
        float flip_p = 0.5f - 0.5f * pp;
        float omp    = 0.5f + 0.5f * pp;
        float r_omt  = rcp(c.omt);
        float r_flip = rcp(c.flip_t);
        // qt[ab][x1] = Qt0[x1,1] * Qt[t-1][ab,1] / Qt[t][ab,x1]
        c.qt00 = 0.01f * flip_p * r_omt;
        c.qt01 = 0.99f * flip_p * r_flip;
        c.qt10 = 0.01f * omp    * r_flip;
        c.qt11 = 0.99f * omp    * r_omt;
    }

    const int*   s_adj = (const int*)sbuf;
    const float* s_u   = (const float*)(sbuf + W_U * 4);
    const float* s_q   = (const float*)(sbuf + W_Q * 4);

    float s = 0.0f;
    {   // row B: 4-element vector groups (nfB in [256, 511])
        const int nfB = g.iB >> 2, remB = g.iB & 3;
        const int4*   aB4 = reinterpret_cast<const int4*>(s_adj + g.cA4);
        const float4* uB4 = reinterpret_cast<const float4*>(s_u + g.cA4);
        const float*  qB  = s_q + g.cqA4 + g.ofsB;
        s += term4(aB4[tid], uB4[tid], qB + (tid << 2), c);      // always full
        const int g1 = tid + 256;
        if (g1 < nfB) s += term4(aB4[g1], uB4[g1], qB + (g1 << 2), c);
        if (tid < remB) {
            int e = (nfB << 2) + tid;
            s += term(s_adj[g.cA4 + e], s_u[g.cA4 + e], qB[e], c);
        }
    }
    {   // row A: 4-element vector groups (nfA <= 255)
        const int nfA = g.iA >> 2, remA = g.iA & 3;
        const int4*   aA4 = reinterpret_cast<const int4*>(s_adj);
        const float4* uA4 = reinterpret_cast<const float4*>(s_u);
        const float*  qA  = s_q + g.ofsA;
        if (tid < nfA) s += term4(aA4[tid], uA4[tid], qA + (tid << 2), c);
        if (tid < remA) {
            int e = (nfA << 2) + tid;
            s += term(s_adj[e], s_u[e], qA[e], c);
        }
    }
    return s;
}

// Persistent CTAs (grid = 148x4), double-buffered TMA-bulk pipeline across
// pairs: one thread stages pair j+1 (6 bulk copies + mbarrier expect_tx),
// all threads wait parity on pair j's mbarrier, then compute pair j.
__global__ __launch_bounds__(NTHR, 4)
void loss_kernel(const int* __restrict__ adj, const int* __restrict__ t,
                 const float* __restrict__ u, const float* __restrict__ q,
                 float* __restrict__ out) {
    extern __shared__ char smem[];
    __shared__ alignas(8) uint64_t mbars[2];
    __shared__ float warp_sums[8];
    __shared__ bool  is_last;

    const int tid  = threadIdx.x;
    const int bidx = blockIdx.x;
    const uint32_t s0   = (uint32_t)__cvta_generic_to_shared(smem);
    const uint32_t mb0  = (uint32_t)__cvta_generic_to_shared(&mbars[0]);
    const uint32_t mb1  = (uint32_t)__cvta_generic_to_shared(&mbars[1]);

    const int npairs = (NPAIR - 1 - bidx) / GRID + 1;   // 7 or 6

    if (tid == 0) { mbar_init(mb0, 1); mbar_init(mb1, 1); }
    __syncthreads();

    int  pid = bidx;
    Geom gcur = mk_geom(pid);
    if (tid == 0) produce(gcur, adj, u, q, s0, mb0);

    float s = 0.0f;
    for (int j = 0; j < npairs; ++j) {
        if (j) __syncthreads();                 // slot (j+1)&1 fully consumed before refill
        Geom gnext;
        if (j + 1 < npairs) {
            gnext = mk_geom(pid + GRID);
            if (tid == 0)
                produce(gnext, adj, u, q,
                        s0 + (uint32_t)(((j + 1) & 1) * BUFB),
                        ((j + 1) & 1) ? mb1 : mb0);
        }
        const int sl = j & 1;
        mbar_wait(sl ? mb1 : mb0, (uint32_t)((j >> 1) & 1));   // pair j staged
        s += compute_pair(gcur, smem + sl * BUFB, t, tid);
        gcur = gnext;
        pid += GRID;
    }

    // Block reduction
    #pragma unroll
    for (int off = 16; off; off >>= 1) s += __shfl_down_sync(0xffffffffu, s, off);
    const int lane = tid & 31, wid = tid >> 5;
    if (lane == 0) warp_sums[wid] = s;
    __syncthreads();
    if (wid == 0) {
        s = (lane < 8) ? warp_sums[lane] : 0.0f;
        #pragma unroll
        for (int off = 4; off; off >>= 1) s += __shfl_down_sync(0xffffffffu, s, off);
        if (lane == 0) g_partials[bidx] = s;
    }

    // Last-block-standing final reduction (counter wraps to 0 -> replayable)
    __threadfence();
    if (tid == 0) {
        unsigned v = atomicInc(&g_count, GRID - 1);
        is_last = (v == GRID - 1);
    }
    __syncthreads();
    if (is_last) {
        float acc = 0.0f;
        for (int idx = tid; idx < GRID; idx += NTHR) acc += g_partials[idx];
        #pragma unroll
        for (int off = 16; off; off >>= 1) acc += __shfl_down_sync(0xffffffffu, acc, off);
        if (lane == 0) warp_sums[wid] = acc;
        __syncthreads();
        if (wid == 0) {
            acc = (lane < 8) ? warp_sums[lane] : 0.0f;
            #pragma unroll
            for (int off = 4; off; off >>= 1) acc += __shfl_down_sync(0xffffffffu, acc, off);
            if (lane == 0) out[0] = acc * (1.0f / (float)(B * E));
        }
    }
}

extern "C" void kernel_launch(void* const* d_in, const int* in_sizes, int n_in,
                              void* d_out, int out_size) {
    // metadata order: adj_start (int32), t (int32), u (f32), q_approx (f32)
    const int*   adj = (const int*)d_in[0];
    const int*   t   = (const int*)d_in[1];
    const float* u   = (const float*)d_in[2];
    const float* q   = (const float*)d_in[3];
    float* out = (float*)d_out;

    // Function attributes (context-level, capture-legal, no allocation).
    cudaFuncSetAttribute(loss_kernel,
                         cudaFuncAttributeMaxDynamicSharedMemorySize, SMEM_DYN);
    cudaFuncSetAttribute(loss_kernel,
                         cudaFuncAttributePreferredSharedMemoryCarveout,
                         cudaSharedmemCarveoutMaxShared);

    loss_kernel<<<GRID, NTHR, SMEM_DYN>>>(adj, t, u, q, out);
}